// round 15
// baseline (speedup 1.0000x reference)
#include <cuda_runtime.h>
#include <cuda_fp16.h>
#include <cstdint>

#define N_NODES 10000
#define DIN 128
#define H1 8
#define F1 64
#define C1 512            // H1*F1
#define E0 80000
#define NE (2*E0 + N_NODES)   // 170000
#define F2 64
#define NEG_SLOPE 0.2f
#define FULL 0xffffffffu
#define NXP (N_NODES*(DIN/2))    // 640000
#define ZK2 4                    // gemm2 split-K planes

// ---------------- scratch (static device globals; no allocation) -------------
static __device__ int      g_src[NE];
static __device__ int      g_dst[NE];
static __device__ int      g_cnt[N_NODES];
static __device__ int      g_cursor[N_NODES];
static __device__ int      g_rowptr[N_NODES + 1];
static __device__ int      g_nbr[NE];              // CSR by dst: src indices
static __device__ uint32_t g_XH[NXP];              // x fp16-split hi, [n][kpair]
static __device__ uint32_t g_XL[NXP];              // x fp16-split lo
static __device__ uint32_t g_B1H[(DIN/2)*C1];      // W1 fp16 plane, kpair-major
static __device__ uint32_t g_B2H[(C1/2)*F2];       // W2 fp16 plane, kpair-major
static __device__ __half2  g_P1h[N_NODES*(C1/2)];  // proj1 as fp16 pairs (gather feed)
static __device__ float    g_as1[N_NODES*H1];
static __device__ float    g_an1[N_NODES*H1];
static __device__ uint32_t g_HH[N_NODES*(C1/2)];   // hbuf fp16-split hi (from gather1)
static __device__ uint32_t g_HL[N_NODES*(C1/2)];   // hbuf fp16-split lo
static __device__ float    g_p2part[ZK2*N_NODES*F2]; // gemm2 split-K partials
static __device__ float    g_proj2[N_NODES*F2];
static __device__ float    g_as2[N_NODES];
static __device__ float    g_an2[N_NODES];

// fp16 split: v = hi + lo
__device__ __forceinline__ void split_pack_f16(float v0, float v1,
                                               uint32_t& hi, uint32_t& lo) {
    __half2 h2 = __floats2half2_rn(v0, v1);
    float r0 = v0 - __half2float(__low2half(h2));
    float r1 = v1 - __half2float(__high2half(h2));
    __half2 l2 = __floats2half2_rn(r0, r1);
    hi = *(const uint32_t*)&h2;
    lo = *(const uint32_t*)&l2;
}

// ---------------- prep A: edge decode + degree count (stream 2) --------------
__global__ void prep_edges(const int* __restrict__ e32) {
    int i = blockIdx.x * blockDim.x + threadIdx.x;
    if (i >= NE) return;
    bool is64 = (e32[1] == 0) && (e32[3] == 0) && (e32[5] == 0) && (e32[7] == 0);
    int s, d;
    if (i < NE - N_NODES) {
        int j  = (i < E0) ? i : (i - E0);
        int si = (i < E0) ? j : (E0 + j);
        int di = (i < E0) ? (E0 + j) : j;
        s = is64 ? e32[2*si] : e32[si];
        d = is64 ? e32[2*di] : e32[di];
    } else {
        s = i - (NE - N_NODES); d = s;
    }
    s = min(max(s, 0), N_NODES - 1);
    d = min(max(d, 0), N_NODES - 1);
    g_src[i] = s; g_dst[i] = d;
    atomicAdd(&g_cnt[d], 1);
}

// ---------------- prep B: x fp16-split (vectorized) + W1/W2 fp16 -------------
__global__ void prep_splits(const float* __restrict__ W1,
                            const float* __restrict__ W2,
                            const float* __restrict__ x) {
    int i = blockIdx.x * blockDim.x + threadIdx.x;
    if (i < NXP/2) {                     // 2 kpairs per thread via float4
        float4 v = *(const float4*)&x[4*i];
        uint32_t h0, l0, h1, l1;
        split_pack_f16(v.x, v.y, h0, l0);
        split_pack_f16(v.z, v.w, h1, l1);
        *(uint2*)&g_XH[2*i] = make_uint2(h0, h1);
        *(uint2*)&g_XL[2*i] = make_uint2(l0, l1);
    }
    if (i < (DIN/2)*C1) {
        int kp = i / C1, c = i % C1;
        int h = c >> 6, f = c & 63;
        __half2 h2 = __floats2half2_rn(W1[(h*DIN + 2*kp)*F1 + f],
                                       W1[(h*DIN + 2*kp + 1)*F1 + f]);
        g_B1H[i] = *(const uint32_t*)&h2;
    }
    if (i < (C1/2)*F2) {
        int kp = i / F2, c = i % F2;
        __half2 h2 = __floats2half2_rn(W2[(2*kp)*F2 + c],
                                       W2[(2*kp + 1)*F2 + c]);
        g_B2H[i] = *(const uint32_t*)&h2;
    }
}

// ---------------- exclusive scan of in-degrees (single block) ----------------
__global__ void scan_kernel() {
    __shared__ int ssum[1024];
    const int t = threadIdx.x;
    const int per = (N_NODES + 1023) / 1024;   // 10
    int base = t * per;
    int loc[16];
    int s = 0;
#pragma unroll
    for (int i = 0; i < per; i++) {
        int idx = base + i;
        int v = (idx < N_NODES) ? g_cnt[idx] : 0;
        loc[i] = v; s += v;
    }
    ssum[t] = s;
    __syncthreads();
    for (int off = 1; off < 1024; off <<= 1) {
        int v = (t >= off) ? ssum[t - off] : 0;
        __syncthreads();
        ssum[t] += v;
        __syncthreads();
    }
    int run = (t > 0) ? ssum[t - 1] : 0;
#pragma unroll
    for (int i = 0; i < per; i++) {
        int idx = base + i;
        if (idx < N_NODES) { g_rowptr[idx] = run; g_cursor[idx] = run; run += loc[i]; }
    }
    if (t == 1023) g_rowptr[N_NODES] = NE;
}

__global__ void fill_csr() {
    int e = blockIdx.x * blockDim.x + threadIdx.x;
    if (e >= NE) return;
    int d = g_dst[e];
    int slot = atomicAdd(&g_cursor[d], 1);
    g_nbr[slot] = g_src[e];
}

// ---------------- fp16 tensor-core MMA (m16n8k16) -----------------------------
#define MMA_F16(D, A0, A1, A2, A3, B0, B1) \
    asm("mma.sync.aligned.m16n8k16.row.col.f32.f16.f16.f32 " \
        "{%0,%1,%2,%3}, {%4,%5,%6,%7}, {%8,%9}, {%0,%1,%2,%3};" \
        : "+f"(D[0]), "+f"(D[1]), "+f"(D[2]), "+f"(D[3]) \
        : "r"(A0), "r"(A1), "r"(A2), "r"(A3), "r"(B0), "r"(B1))

// ---------------- GEMM1: persistent 64-row A tile, loop 8 heads x 8 K-chunks -
// A loaded ONCE per CTA (was 8x, once per head-CTA). B double-buffered via regs.
// Fused alpha1 per head. 157 CTAs.
__global__ __launch_bounds__(256) void gemm1_kernel(const float* __restrict__ a1) {
    __shared__ uint32_t AsH[64][68], AsL[64][68];   // stride 68: conflict-free frags
    __shared__ uint32_t Bs[2][64][12];
    __shared__ float sAs[H1][64], sAn[H1][64];
    __shared__ float salS[64][2], salN[64][2];

    const int tid = threadIdx.x;
    const int lane = tid & 31, wid = tid >> 5;
    const int wm = wid >> 1, wn = wid & 1;          // 4 m-groups x 2 n-groups
    const int g = lane >> 2, tig = lane & 3;
    const int row0 = blockIdx.x * 64;
    const int M = N_NODES;

    // prologue: a1 -> smem (8 heads x 128 floats)
#pragma unroll
    for (int t = 0; t < 4; t++) {
        int idx = tid + t*256;
        int h = idx >> 7, r = idx & 127;
        float v = __ldg(&a1[idx]);
        if (r < 64) sAs[h][r] = v; else sAn[h][r - 64] = v;
    }
    // prologue: persistent A tile, both planes (uint2 loads, 8/thread)
#pragma unroll
    for (int t = 0; t < 8; t++) {
        int idx = tid + t*256;                 // 0..2047
        int r = idx >> 5, kp2 = (idx & 31) * 2;
        int grow = row0 + r;
        uint2 vh = make_uint2(0u, 0u), vl = make_uint2(0u, 0u);
        if (grow < M) {
            vh = *(const uint2*)&g_XH[(size_t)grow*(DIN/2) + kp2];
            vl = *(const uint2*)&g_XL[(size_t)grow*(DIN/2) + kp2];
        }
        AsH[r][kp2] = vh.x;  AsH[r][kp2 + 1] = vh.y;
        AsL[r][kp2] = vl.x;  AsL[r][kp2 + 1] = vl.y;
    }
    // prologue: B tile for q=0 (h=0, kpb=0)
    {
        int kk0 = tid >> 6, c0 = tid & 63;
        Bs[0][c0][kk0] = g_B1H[(size_t)kk0*C1 + c0];
        int idx = tid + 256;
        int kk1 = idx >> 6, c1 = idx & 63;
        Bs[0][c1][kk1] = g_B1H[(size_t)kk1*C1 + c1];
    }
    __syncthreads();

    float acc[4][4];
#pragma unroll
    for (int ni = 0; ni < 4; ni++)
#pragma unroll
        for (int q = 0; q < 4; q++) acc[ni][q] = 0.f;

    const int r = wm*16 + g;    // warp's A row (and r+8)
    int p = 0;
    for (int q = 0; q < H1*8; q++) {
        const int h = q >> 3, it = q & 7;
        const int kpb = it * 8;

        // prefetch B(q+1) into regs
        uint32_t pb0 = 0u, pb1 = 0u;
        if (q < H1*8 - 1) {
            int q1 = q + 1, h1 = q1 >> 3, it1 = q1 & 7;
            int kpb1 = it1 * 8, col1 = h1 * 64;
            int i0 = tid, i1 = tid + 256;
            pb0 = g_B1H[(size_t)(kpb1 + (i0 >> 6))*C1 + col1 + (i0 & 63)];
            pb1 = g_B1H[(size_t)(kpb1 + (i1 >> 6))*C1 + col1 + (i1 & 63)];
        }

        // fragments + MMAs
        uint32_t bh[4][2];
#pragma unroll
        for (int ni = 0; ni < 4; ni++) {
            int c = wn*32 + ni*8 + g;
            bh[ni][0] = Bs[p][c][tig];
            bh[ni][1] = Bs[p][c][tig + 4];
        }
        uint32_t ah0 = AsH[r][kpb + tig],     ah1 = AsH[r + 8][kpb + tig];
        uint32_t ah2 = AsH[r][kpb + tig + 4], ah3 = AsH[r + 8][kpb + tig + 4];
        uint32_t al0 = AsL[r][kpb + tig],     al1 = AsL[r + 8][kpb + tig];
        uint32_t al2 = AsL[r][kpb + tig + 4], al3 = AsL[r + 8][kpb + tig + 4];
#pragma unroll
        for (int ni = 0; ni < 4; ni++) {
            MMA_F16(acc[ni], ah0, ah1, ah2, ah3, bh[ni][0], bh[ni][1]);
            MMA_F16(acc[ni], al0, al1, al2, al3, bh[ni][0], bh[ni][1]);
        }

        // per-head epilogue (uniform branch)
        if (it == 7) {
            const int col0 = h * 64;
            float s0 = 0.f, s8 = 0.f, n0 = 0.f, n8 = 0.f;
            int growA = row0 + r, growB = growA + 8;
#pragma unroll
            for (int ni = 0; ni < 4; ni++) {
                float c0 = acc[ni][0], c1 = acc[ni][1];
                float c2 = acc[ni][2], c3 = acc[ni][3];
                int cl = wn*32 + ni*8 + 2*tig;
                size_t cp = (size_t)(col0 + cl) >> 1;
                if (growA < M)
                    g_P1h[(size_t)growA*(C1/2) + cp] = __floats2half2_rn(c0, c1);
                if (growB < M)
                    g_P1h[(size_t)growB*(C1/2) + cp] = __floats2half2_rn(c2, c3);
                float as0 = sAs[h][cl], as1v = sAs[h][cl + 1];
                float an0 = sAn[h][cl], an1v = sAn[h][cl + 1];
                s0 += c0*as0 + c1*as1v;  n0 += c0*an0 + c1*an1v;
                s8 += c2*as0 + c3*as1v;  n8 += c2*an0 + c3*an1v;
            }
#pragma unroll
            for (int o = 1; o <= 2; o <<= 1) {
                s0 += __shfl_xor_sync(FULL, s0, o);
                s8 += __shfl_xor_sync(FULL, s8, o);
                n0 += __shfl_xor_sync(FULL, n0, o);
                n8 += __shfl_xor_sync(FULL, n8, o);
            }
            if (tig == 0) {
                int rl = wm*16 + g;
                salS[rl][wn] = s0;  salN[rl][wn] = n0;
                salS[rl + 8][wn] = s8;  salN[rl + 8][wn] = n8;
            }
            __syncthreads();
            if (tid < 64) {
                int grow = row0 + tid;
                if (grow < M) {
                    g_as1[grow*H1 + h] = salS[tid][0] + salS[tid][1];
                    g_an1[grow*H1 + h] = salN[tid][0] + salN[tid][1];
                }
            }
#pragma unroll
            for (int ni = 0; ni < 4; ni++)
#pragma unroll
                for (int qq = 0; qq < 4; qq++) acc[ni][qq] = 0.f;
        }

        // commit prefetched B, swap buffers
        if (q < H1*8 - 1) {
            int i0 = tid, i1 = tid + 256;
            Bs[p^1][i0 & 63][i0 >> 6] = pb0;
            Bs[p^1][i1 & 63][i1 >> 6] = pb1;
            __syncthreads();
            p ^= 1;
        }
    }
}

// ---------------- GEMM2: fp16-x2 MMA, split-K z=4, pre-split A ---------------
__global__ __launch_bounds__(256) void gemm2_kernel() {
    __shared__ uint32_t AsH[128][12], AsL[128][12];
    __shared__ uint32_t BsH[64][12];

    const int tid = threadIdx.x;
    const int lane = tid & 31, wid = tid >> 5;
    const int wm = wid >> 1, wn = wid & 1;
    const int g = lane >> 2, tig = lane & 3;
    const int row0 = blockIdx.y * 128;
    const int z = blockIdx.x;
    const int M = N_NODES;
    float* C = g_p2part + (size_t)z * N_NODES * F2;

    float acc[2][4][4];
#pragma unroll
    for (int mi = 0; mi < 2; mi++)
#pragma unroll
        for (int ni = 0; ni < 4; ni++)
#pragma unroll
            for (int q = 0; q < 4; q++) acc[mi][ni][q] = 0.f;

    const int kbeg = z * (C1/ZK2);
    for (int k0 = kbeg; k0 < kbeg + C1/ZK2; k0 += 16) {
        const int kpb = k0 >> 1;
#pragma unroll
        for (int t = 0; t < 4; t++) {
            int idx = tid + t*256;
            int r = idx >> 3, kk = idx & 7;
            int grow = row0 + r;
            if (grow < M) {
                size_t gi = (size_t)grow*(C1/2) + kpb + kk;
                AsH[r][kk] = g_HH[gi];
                AsL[r][kk] = g_HL[gi];
            } else {
                AsH[r][kk] = 0u; AsL[r][kk] = 0u;
            }
        }
#pragma unroll
        for (int t = 0; t < 2; t++) {
            int idx = tid + t*256;
            int kk = idx >> 6, c = idx & 63;
            BsH[c][kk] = g_B2H[(size_t)(kpb + kk)*F2 + c];
        }
        __syncthreads();

        uint32_t bh[4][2];
#pragma unroll
        for (int ni = 0; ni < 4; ni++) {
            int c = wn*32 + ni*8 + g;
            bh[ni][0] = BsH[c][tig];     bh[ni][1] = BsH[c][tig + 4];
        }
#pragma unroll
        for (int mi = 0; mi < 2; mi++) {
            int r = wm*32 + mi*16 + g;
            uint32_t ah0 = AsH[r][tig],     ah1 = AsH[r + 8][tig];
            uint32_t ah2 = AsH[r][tig + 4], ah3 = AsH[r + 8][tig + 4];
            uint32_t al0 = AsL[r][tig],     al1 = AsL[r + 8][tig];
            uint32_t al2 = AsL[r][tig + 4], al3 = AsL[r + 8][tig + 4];
#pragma unroll
            for (int ni = 0; ni < 4; ni++) {
                MMA_F16(acc[mi][ni], ah0, ah1, ah2, ah3, bh[ni][0], bh[ni][1]);
                MMA_F16(acc[mi][ni], al0, al1, al2, al3, bh[ni][0], bh[ni][1]);
            }
        }
        __syncthreads();
    }

#pragma unroll
    for (int mi = 0; mi < 2; mi++) {
        int growA = row0 + wm*32 + mi*16 + g;
        int growB = growA + 8;
#pragma unroll
        for (int ni = 0; ni < 4; ni++) {
            int cl = wn*32 + ni*8 + 2*tig;
            if (growA < M)
                *(float2*)&C[(size_t)growA*F2 + cl] =
                    make_float2(acc[mi][ni][0], acc[mi][ni][1]);
            if (growB < M)
                *(float2*)&C[(size_t)growB*F2 + cl] =
                    make_float2(acc[mi][ni][2], acc[mi][ni][3]);
        }
    }
}

// ---------------- combine split-K partials + attention (layer 2) -------------
__global__ void alpha2_combine(const float* __restrict__ a2) {
    int t = blockIdx.x * blockDim.x + threadIdx.x;
    int w = t >> 5, lane = t & 31;
    if (w >= N_NODES) return;
    const size_t NF = (size_t)N_NODES * F2;
    size_t base = (size_t)w*F2;
    float v0 = 0.f, v1 = 0.f;
#pragma unroll
    for (int z = 0; z < ZK2; z++) {
        v0 += g_p2part[z*NF + base + lane];
        v1 += g_p2part[z*NF + base + lane + 32];
    }
    g_proj2[base + lane] = v0;
    g_proj2[base + lane + 32] = v1;
    float s  = v0*a2[lane]      + v1*a2[lane + 32];
    float tn = v0*a2[F2 + lane] + v1*a2[F2 + lane + 32];
#pragma unroll
    for (int o = 16; o; o >>= 1) {
        s  += __shfl_xor_sync(FULL, s, o);
        tn += __shfl_xor_sync(FULL, tn, o);
    }
    if (!lane) { g_as2[w] = s; g_an2[w] = tn; }
}

// ---------------- fused gather1: single-pass softmax, fp16-split store -------
__global__ void gather1() {
    int t = blockIdx.x * blockDim.x + threadIdx.x;
    int w = t >> 5, lane = t & 31;
    if (w >= N_NODES*H1) return;
    int n = w >> 3, h = w & 7;
    int beg = g_rowptr[n], end = g_rowptr[n + 1];
    float as = g_as1[n*H1 + h];

    const int half = lane >> 4;
    const int fl2 = (lane & 15) * 2;
    const __half2* projh = g_P1h + h*(F1/2) + fl2;
    float a0 = 0.f, a1v = 0.f, a2v = 0.f, a3 = 0.f, den = 0.f;
    for (int base = beg; base < end; base += 32) {
        int i = base + lane;
        int s = 0; float wgt = 0.f;
        if (i < end) {
            s = g_nbr[i];
            float v = as + g_an1[s*H1 + h];
            v = (v >= 0.f) ? v : NEG_SLOPE*v;
            wgt = __expf(v);
            den += wgt;
        }
        int cnt = min(32, end - base);
        if (cnt == 32) {
#pragma unroll
            for (int j = 0; j < 16; j++) {
                int sl = 2*j + half;
                float ww = __shfl_sync(FULL, wgt, sl);
                int ss = __shfl_sync(FULL, s, sl);
                uint2 u = *(const uint2*)&projh[(size_t)ss*(C1/2)];
                float2 f0 = __half22float2(*reinterpret_cast<__half2*>(&u.x));
                float2 f1 = __half22float2(*reinterpret_cast<__half2*>(&u.y));
                a0 += ww*f0.x; a1v += ww*f0.y; a2v += ww*f1.x; a3 += ww*f1.y;
            }
        } else {
            int jmax = (cnt + 1) >> 1;
            for (int j = 0; j < jmax; j++) {
                int sl = 2*j + half;
                float ww = __shfl_sync(FULL, wgt, sl);
                int ss = __shfl_sync(FULL, s, sl);
                uint2 u = *(const uint2*)&projh[(size_t)ss*(C1/2)];
                float2 f0 = __half22float2(*reinterpret_cast<__half2*>(&u.x));
                float2 f1 = __half22float2(*reinterpret_cast<__half2*>(&u.y));
                a0 += ww*f0.x; a1v += ww*f0.y; a2v += ww*f1.x; a3 += ww*f1.y;
            }
        }
    }
    a0  += __shfl_xor_sync(FULL, a0, 16);
    a1v += __shfl_xor_sync(FULL, a1v, 16);
    a2v += __shfl_xor_sync(FULL, a2v, 16);
    a3  += __shfl_xor_sync(FULL, a3, 16);
#pragma unroll
    for (int o = 16; o; o >>= 1) den += __shfl_xor_sync(FULL, den, o);
    if (lane < 16) {
        float inv = 1.f / den;
        a0 *= inv; a1v *= inv; a2v *= inv; a3 *= inv;
        a0  = (a0  > 0.f) ? a0  : expm1f(a0);
        a1v = (a1v > 0.f) ? a1v : expm1f(a1v);
        a2v = (a2v > 0.f) ? a2v : expm1f(a2v);
        a3  = (a3  > 0.f) ? a3  : expm1f(a3);
        size_t kp0 = (size_t)n*(C1/2) + ((h*F1 + fl2*2) >> 1);
        uint32_t h0, l0, h1, l1;
        split_pack_f16(a0, a1v, h0, l0);
        split_pack_f16(a2v, a3, h1, l1);
        *(uint2*)&g_HH[kp0] = make_uint2(h0, h1);
        *(uint2*)&g_HL[kp0] = make_uint2(l0, l1);
    }
}

// ---------------- fused gather layer 2 (single-pass, fp32 features) ----------
__global__ void gather2(float* __restrict__ out) {
    int t = blockIdx.x * blockDim.x + threadIdx.x;
    int w = t >> 5, lane = t & 31;
    if (w >= N_NODES) return;
    int n = w;
    int beg = g_rowptr[n], end = g_rowptr[n + 1];
    float as = g_as2[n];

    const int half = lane >> 4;
    const int fl = (lane & 15) * 4;
    const float* projl = g_proj2 + fl;
    float a0 = 0.f, a1v = 0.f, a2v = 0.f, a3 = 0.f, den = 0.f;
    for (int base = beg; base < end; base += 32) {
        int i = base + lane;
        int s = 0; float wgt = 0.f;
        if (i < end) {
            s = g_nbr[i];
            float v = as + g_an2[s];
            v = (v >= 0.f) ? v : NEG_SLOPE*v;
            wgt = __expf(v);
            den += wgt;
        }
        int cnt = min(32, end - base);
        if (cnt == 32) {
#pragma unroll
            for (int j = 0; j < 16; j++) {
                int sl = 2*j + half;
                float ww = __shfl_sync(FULL, wgt, sl);
                int ss = __shfl_sync(FULL, s, sl);
                float4 p = *(const float4*)&projl[(size_t)ss*F2];
                a0 += ww*p.x; a1v += ww*p.y; a2v += ww*p.z; a3 += ww*p.w;
            }
        } else {
            int jmax = (cnt + 1) >> 1;
            for (int j = 0; j < jmax; j++) {
                int sl = 2*j + half;
                float ww = __shfl_sync(FULL, wgt, sl);
                int ss = __shfl_sync(FULL, s, sl);
                float4 p = *(const float4*)&projl[(size_t)ss*F2];
                a0 += ww*p.x; a1v += ww*p.y; a2v += ww*p.z; a3 += ww*p.w;
            }
        }
    }
    a0  += __shfl_xor_sync(FULL, a0, 16);
    a1v += __shfl_xor_sync(FULL, a1v, 16);
    a2v += __shfl_xor_sync(FULL, a2v, 16);
    a3  += __shfl_xor_sync(FULL, a3, 16);
#pragma unroll
    for (int o = 16; o; o >>= 1) den += __shfl_xor_sync(FULL, den, o);
    if (lane < 16) {
        float inv = 1.f / den;
        *(float4*)&out[(size_t)n*F2 + fl] =
            make_float4(a0*inv, a1v*inv, a2v*inv, a3*inv);
    }
}

// ---------------- launch -------------------------------------------------------
extern "C" void kernel_launch(void* const* d_in, const int* in_sizes, int n_in,
                              void* d_out, int out_size) {
    const float* x     = (const float*)d_in[0];
    const int*   edges = (const int*)d_in[1];
    const float* W1    = (const float*)d_in[2];
    const float* a1    = (const float*)d_in[3];
    const float* W2    = (const float*)d_in[4];
    const float* a2    = (const float*)d_in[5];
    float* out = (float*)d_out;

    static cudaStream_t s2 = nullptr;
    static cudaEvent_t evFork = nullptr, evCSR = nullptr;
    if (s2 == nullptr) {
        cudaStreamCreateWithFlags(&s2, cudaStreamNonBlocking);
        cudaEventCreateWithFlags(&evFork, cudaEventDisableTiming);
        cudaEventCreateWithFlags(&evCSR, cudaEventDisableTiming);
    }

    void* cnt_ptr = nullptr;
    cudaGetSymbolAddress(&cnt_ptr, g_cnt);

    // fork: CSR build on s2, concurrent with split+gemm1 on main stream
    cudaEventRecord(evFork, 0);
    cudaStreamWaitEvent(s2, evFork, 0);

    cudaMemsetAsync(cnt_ptr, 0, N_NODES*sizeof(int), s2);
    prep_edges<<<(NE + 255)/256, 256, 0, s2>>>(edges);
    scan_kernel<<<1, 1024, 0, s2>>>();
    fill_csr<<<(NE + 255)/256, 256, 0, s2>>>();
    cudaEventRecord(evCSR, s2);

    prep_splits<<<(NXP/2 + 255)/256, 256>>>(W1, W2, x);
    gemm1_kernel<<<(N_NODES + 63)/64, 256>>>(a1);

    // join: gather1 needs CSR + gemm1
    cudaStreamWaitEvent(0, evCSR, 0);
    gather1<<<(N_NODES*H1*32 + 255)/256, 256>>>();

    // layer 2
    gemm2_kernel<<<dim3(ZK2, (N_NODES + 127)/128), 256>>>();
    alpha2_combine<<<(N_NODES*32 + 255)/256, 256>>>(a2);
    gather2<<<(N_NODES*32 + 255)/256, 256>>>(out);
}

// round 16
// speedup vs baseline: 1.0660x; 1.0660x over previous
#include <cuda_runtime.h>
#include <cuda_fp16.h>
#include <cstdint>

#define N_NODES 10000
#define DIN 128
#define H1 8
#define F1 64
#define C1 512            // H1*F1
#define E0 80000
#define NE (2*E0 + N_NODES)   // 170000
#define F2 64
#define NEG_SLOPE 0.2f
#define FULL 0xffffffffu
#define NXP (N_NODES*(DIN/2))    // 640000
#define ZK2 4                    // gemm2 split-K planes

// ---------------- scratch (static device globals; no allocation) -------------
static __device__ int      g_src[NE];
static __device__ int      g_dst[NE];
static __device__ int      g_cnt[N_NODES];
static __device__ int      g_cursor[N_NODES];
static __device__ int      g_rowptr[N_NODES + 1];
static __device__ int      g_nbr[NE];              // CSR by dst: src indices
static __device__ uint32_t g_XH[NXP];              // x fp16-split hi, [n][kpair]
static __device__ uint32_t g_XL[NXP];              // x fp16-split lo
static __device__ uint32_t g_B1H[(DIN/2)*C1];      // W1 fp16 plane, kpair-major
static __device__ uint32_t g_B2H[(C1/2)*F2];       // W2 fp16 plane, kpair-major
static __device__ __half2  g_P1h[N_NODES*(C1/2)];  // proj1 as fp16 pairs (gather feed)
static __device__ float    g_as1[N_NODES*H1];
static __device__ float    g_an1[N_NODES*H1];
static __device__ uint32_t g_HH[N_NODES*(C1/2)];   // hbuf fp16-split hi (from gather1)
static __device__ uint32_t g_HL[N_NODES*(C1/2)];   // hbuf fp16-split lo
static __device__ float    g_p2part[ZK2*N_NODES*F2]; // gemm2 split-K partials
static __device__ float    g_proj2[N_NODES*F2];
static __device__ float    g_as2[N_NODES];
static __device__ float    g_an2[N_NODES];

// fp16 split: v = hi + lo
__device__ __forceinline__ void split_pack_f16(float v0, float v1,
                                               uint32_t& hi, uint32_t& lo) {
    __half2 h2 = __floats2half2_rn(v0, v1);
    float r0 = v0 - __half2float(__low2half(h2));
    float r1 = v1 - __half2float(__high2half(h2));
    __half2 l2 = __floats2half2_rn(r0, r1);
    hi = *(const uint32_t*)&h2;
    lo = *(const uint32_t*)&l2;
}

// ---------------- prep A: edges + degree + W2 fp16 (stream 2) ----------------
__global__ void prep_edges(const int* __restrict__ e32,
                           const float* __restrict__ W2) {
    int i = blockIdx.x * blockDim.x + threadIdx.x;
    if (i < NE) {
        bool is64 = (e32[1] == 0) && (e32[3] == 0) && (e32[5] == 0) && (e32[7] == 0);
        int s, d;
        if (i < NE - N_NODES) {
            int j  = (i < E0) ? i : (i - E0);
            int si = (i < E0) ? j : (E0 + j);
            int di = (i < E0) ? (E0 + j) : j;
            s = is64 ? e32[2*si] : e32[si];
            d = is64 ? e32[2*di] : e32[di];
        } else {
            s = i - (NE - N_NODES); d = s;
        }
        s = min(max(s, 0), N_NODES - 1);
        d = min(max(d, 0), N_NODES - 1);
        g_src[i] = s; g_dst[i] = d;
        atomicAdd(&g_cnt[d], 1);
    }
    // W2 (C1,F2) -> fp16 plane, kpair-major  ((C1/2)*F2 = 16384 < NE)
    if (i < (C1/2)*F2) {
        int kp = i / F2, c = i % F2;
        __half2 h2 = __floats2half2_rn(W2[(2*kp)*F2 + c],
                                       W2[(2*kp + 1)*F2 + c]);
        g_B2H[i] = *(const uint32_t*)&h2;
    }
}

// ---------------- prep B: x fp16-split (MLP=4) + W1 fp16 (main stream) -------
// 4 independent float4 loads per thread -> latency fully overlapped.
__global__ void prep_splits(const float* __restrict__ W1,
                            const float* __restrict__ x) {
    int i = blockIdx.x * blockDim.x + threadIdx.x;
    const int NQ = NXP/2;                 // 320000 float4-quads
    if (i < NQ/4 * 4) { /* no-op shape hint */ }
    // x: each thread handles 4 quads strided by total/4
    {
        const int stride = (NQ + 3) / 4;  // 80000
        float4 v[4];
        int idx[4];
#pragma unroll
        for (int t = 0; t < 4; t++) {
            idx[t] = i + t*stride;
            if (idx[t] < NQ) v[t] = *(const float4*)&x[4*idx[t]];
        }
#pragma unroll
        for (int t = 0; t < 4; t++) {
            if (idx[t] < NQ) {
                uint32_t h0, l0, h1, l1;
                split_pack_f16(v[t].x, v[t].y, h0, l0);
                split_pack_f16(v[t].z, v[t].w, h1, l1);
                *(uint2*)&g_XH[2*idx[t]] = make_uint2(h0, h1);
                *(uint2*)&g_XL[2*idx[t]] = make_uint2(l0, l1);
            }
        }
    }
    if (i < (DIN/2)*C1) {
        int kp = i / C1, c = i % C1;
        int h = c >> 6, f = c & 63;
        __half2 h2 = __floats2half2_rn(W1[(h*DIN + 2*kp)*F1 + f],
                                       W1[(h*DIN + 2*kp + 1)*F1 + f]);
        g_B1H[i] = *(const uint32_t*)&h2;
    }
}

// ---------------- exclusive scan of in-degrees (single block) ----------------
__global__ void scan_kernel() {
    __shared__ int ssum[1024];
    const int t = threadIdx.x;
    const int per = (N_NODES + 1023) / 1024;   // 10
    int base = t * per;
    int loc[16];
    int s = 0;
#pragma unroll
    for (int i = 0; i < per; i++) {
        int idx = base + i;
        int v = (idx < N_NODES) ? g_cnt[idx] : 0;
        loc[i] = v; s += v;
    }
    ssum[t] = s;
    __syncthreads();
    for (int off = 1; off < 1024; off <<= 1) {
        int v = (t >= off) ? ssum[t - off] : 0;
        __syncthreads();
        ssum[t] += v;
        __syncthreads();
    }
    int run = (t > 0) ? ssum[t - 1] : 0;
#pragma unroll
    for (int i = 0; i < per; i++) {
        int idx = base + i;
        if (idx < N_NODES) { g_rowptr[idx] = run; g_cursor[idx] = run; run += loc[i]; }
    }
    if (t == 1023) g_rowptr[N_NODES] = NE;
}

__global__ void fill_csr() {
    int e = blockIdx.x * blockDim.x + threadIdx.x;
    if (e >= NE) return;
    int d = g_dst[e];
    int slot = atomicAdd(&g_cursor[d], 1);
    g_nbr[slot] = g_src[e];
}

// ---------------- fp16 tensor-core MMA (m16n8k16) -----------------------------
#define MMA_F16(D, A0, A1, A2, A3, B0, B1) \
    asm("mma.sync.aligned.m16n8k16.row.col.f32.f16.f16.f32 " \
        "{%0,%1,%2,%3}, {%4,%5,%6,%7}, {%8,%9}, {%0,%1,%2,%3};" \
        : "+f"(D[0]), "+f"(D[1]), "+f"(D[2]), "+f"(D[3]) \
        : "r"(A0), "r"(A1), "r"(A2), "r"(A3), "r"(B0), "r"(B1))

// ---------------- GEMM1: 128x64 tile, fp16-x2 split, fused alpha1 (R14) ------
__global__ __launch_bounds__(256) void gemm1_kernel(const float* __restrict__ a1) {
    __shared__ uint32_t AsH[128][12], AsL[128][12];
    __shared__ uint32_t BsH[64][12];
    __shared__ float sAs[64], sAn[64];
    __shared__ float salS[128][2], salN[128][2];

    const int tid = threadIdx.x;
    const int lane = tid & 31, wid = tid >> 5;
    const int wm = wid >> 1, wn = wid & 1;
    const int g = lane >> 2, tig = lane & 3;
    const int row0 = blockIdx.y * 128;
    const int h = blockIdx.x;
    const int col0 = h * 64;
    const int M = N_NODES;

    if (tid < 64) {
        sAs[tid] = __ldg(&a1[h*2*F1 + tid]);
        sAn[tid] = __ldg(&a1[h*2*F1 + F1 + tid]);
    }

    float acc[2][4][4];
#pragma unroll
    for (int mi = 0; mi < 2; mi++)
#pragma unroll
        for (int ni = 0; ni < 4; ni++)
#pragma unroll
            for (int q = 0; q < 4; q++) acc[mi][ni][q] = 0.f;

    for (int k0 = 0; k0 < DIN; k0 += 16) {
        const int kpb = k0 >> 1;
#pragma unroll
        for (int t = 0; t < 4; t++) {
            int idx = tid + t*256;
            int r = idx >> 3, kk = idx & 7;
            int grow = row0 + r;
            if (grow < M) {
                size_t gi = (size_t)grow*(DIN/2) + kpb + kk;
                AsH[r][kk] = g_XH[gi];
                AsL[r][kk] = g_XL[gi];
            } else {
                AsH[r][kk] = 0u; AsL[r][kk] = 0u;
            }
        }
#pragma unroll
        for (int t = 0; t < 2; t++) {
            int idx = tid + t*256;
            int kk = idx >> 6, c = idx & 63;
            BsH[c][kk] = g_B1H[(size_t)(kpb + kk)*C1 + col0 + c];
        }
        __syncthreads();

        uint32_t bh[4][2];
#pragma unroll
        for (int ni = 0; ni < 4; ni++) {
            int c = wn*32 + ni*8 + g;
            bh[ni][0] = BsH[c][tig];     bh[ni][1] = BsH[c][tig + 4];
        }
#pragma unroll
        for (int mi = 0; mi < 2; mi++) {
            int r = wm*32 + mi*16 + g;
            uint32_t ah0 = AsH[r][tig],     ah1 = AsH[r + 8][tig];
            uint32_t ah2 = AsH[r][tig + 4], ah3 = AsH[r + 8][tig + 4];
            uint32_t al0 = AsL[r][tig],     al1 = AsL[r + 8][tig];
            uint32_t al2 = AsL[r][tig + 4], al3 = AsL[r + 8][tig + 4];
#pragma unroll
            for (int ni = 0; ni < 4; ni++) {
                MMA_F16(acc[mi][ni], ah0, ah1, ah2, ah3, bh[ni][0], bh[ni][1]);
                MMA_F16(acc[mi][ni], al0, al1, al2, al3, bh[ni][0], bh[ni][1]);
            }
        }
        __syncthreads();
    }

    // epilogue: fp16 proj1 store + fused alpha1 (fp32)
#pragma unroll
    for (int mi = 0; mi < 2; mi++) {
        float s0 = 0.f, s8 = 0.f, n0 = 0.f, n8 = 0.f;
        int growA = row0 + wm*32 + mi*16 + g;
        int growB = growA + 8;
#pragma unroll
        for (int ni = 0; ni < 4; ni++) {
            float c0 = acc[mi][ni][0], c1 = acc[mi][ni][1];
            float c2 = acc[mi][ni][2], c3 = acc[mi][ni][3];
            int cl = wn*32 + ni*8 + 2*tig;
            size_t cp = (size_t)(col0 + cl) >> 1;
            if (growA < M)
                g_P1h[(size_t)growA*(C1/2) + cp] = __floats2half2_rn(c0, c1);
            if (growB < M)
                g_P1h[(size_t)growB*(C1/2) + cp] = __floats2half2_rn(c2, c3);
            float as0 = sAs[cl], as1 = sAs[cl + 1];
            float an0 = sAn[cl], an1 = sAn[cl + 1];
            s0 += c0*as0 + c1*as1;  n0 += c0*an0 + c1*an1;
            s8 += c2*as0 + c3*as1;  n8 += c2*an0 + c3*an1;
        }
#pragma unroll
        for (int o = 1; o <= 2; o <<= 1) {
            s0 += __shfl_xor_sync(FULL, s0, o);
            s8 += __shfl_xor_sync(FULL, s8, o);
            n0 += __shfl_xor_sync(FULL, n0, o);
            n8 += __shfl_xor_sync(FULL, n8, o);
        }
        if (tig == 0) {
            int rl = wm*32 + mi*16 + g;
            salS[rl][wn] = s0;  salN[rl][wn] = n0;
            salS[rl + 8][wn] = s8;  salN[rl + 8][wn] = n8;
        }
    }
    __syncthreads();
    if (tid < 128) {
        int grow = row0 + tid;
        if (grow < M) {
            g_as1[grow*H1 + h] = salS[tid][0] + salS[tid][1];
            g_an1[grow*H1 + h] = salN[tid][0] + salN[tid][1];
        }
    }
}

// ---------------- GEMM2: fp16-x2 MMA, split-K z=4, pre-split A (R14) ---------
__global__ __launch_bounds__(256) void gemm2_kernel() {
    __shared__ uint32_t AsH[128][12], AsL[128][12];
    __shared__ uint32_t BsH[64][12];

    const int tid = threadIdx.x;
    const int lane = tid & 31, wid = tid >> 5;
    const int wm = wid >> 1, wn = wid & 1;
    const int g = lane >> 2, tig = lane & 3;
    const int row0 = blockIdx.y * 128;
    const int z = blockIdx.x;
    const int M = N_NODES;
    float* C = g_p2part + (size_t)z * N_NODES * F2;

    float acc[2][4][4];
#pragma unroll
    for (int mi = 0; mi < 2; mi++)
#pragma unroll
        for (int ni = 0; ni < 4; ni++)
#pragma unroll
            for (int q = 0; q < 4; q++) acc[mi][ni][q] = 0.f;

    const int kbeg = z * (C1/ZK2);
    for (int k0 = kbeg; k0 < kbeg + C1/ZK2; k0 += 16) {
        const int kpb = k0 >> 1;
#pragma unroll
        for (int t = 0; t < 4; t++) {
            int idx = tid + t*256;
            int r = idx >> 3, kk = idx & 7;
            int grow = row0 + r;
            if (grow < M) {
                size_t gi = (size_t)grow*(C1/2) + kpb + kk;
                AsH[r][kk] = g_HH[gi];
                AsL[r][kk] = g_HL[gi];
            } else {
                AsH[r][kk] = 0u; AsL[r][kk] = 0u;
            }
        }
#pragma unroll
        for (int t = 0; t < 2; t++) {
            int idx = tid + t*256;
            int kk = idx >> 6, c = idx & 63;
            BsH[c][kk] = g_B2H[(size_t)(kpb + kk)*F2 + c];
        }
        __syncthreads();

        uint32_t bh[4][2];
#pragma unroll
        for (int ni = 0; ni < 4; ni++) {
            int c = wn*32 + ni*8 + g;
            bh[ni][0] = BsH[c][tig];     bh[ni][1] = BsH[c][tig + 4];
        }
#pragma unroll
        for (int mi = 0; mi < 2; mi++) {
            int r = wm*32 + mi*16 + g;
            uint32_t ah0 = AsH[r][tig],     ah1 = AsH[r + 8][tig];
            uint32_t ah2 = AsH[r][tig + 4], ah3 = AsH[r + 8][tig + 4];
            uint32_t al0 = AsL[r][tig],     al1 = AsL[r + 8][tig];
            uint32_t al2 = AsL[r][tig + 4], al3 = AsL[r + 8][tig + 4];
#pragma unroll
            for (int ni = 0; ni < 4; ni++) {
                MMA_F16(acc[mi][ni], ah0, ah1, ah2, ah3, bh[ni][0], bh[ni][1]);
                MMA_F16(acc[mi][ni], al0, al1, al2, al3, bh[ni][0], bh[ni][1]);
            }
        }
        __syncthreads();
    }

#pragma unroll
    for (int mi = 0; mi < 2; mi++) {
        int growA = row0 + wm*32 + mi*16 + g;
        int growB = growA + 8;
#pragma unroll
        for (int ni = 0; ni < 4; ni++) {
            int cl = wn*32 + ni*8 + 2*tig;
            if (growA < M)
                *(float2*)&C[(size_t)growA*F2 + cl] =
                    make_float2(acc[mi][ni][0], acc[mi][ni][1]);
            if (growB < M)
                *(float2*)&C[(size_t)growB*F2 + cl] =
                    make_float2(acc[mi][ni][2], acc[mi][ni][3]);
        }
    }
}

// ---------------- combine split-K partials + attention (layer 2) -------------
__global__ void alpha2_combine(const float* __restrict__ a2) {
    int t = blockIdx.x * blockDim.x + threadIdx.x;
    int w = t >> 5, lane = t & 31;
    if (w >= N_NODES) return;
    const size_t NF = (size_t)N_NODES * F2;
    size_t base = (size_t)w*F2;
    float v0 = 0.f, v1 = 0.f;
#pragma unroll
    for (int z = 0; z < ZK2; z++) {
        v0 += g_p2part[z*NF + base + lane];
        v1 += g_p2part[z*NF + base + lane + 32];
    }
    g_proj2[base + lane] = v0;
    g_proj2[base + lane + 32] = v1;
    float s  = v0*a2[lane]      + v1*a2[lane + 32];
    float tn = v0*a2[F2 + lane] + v1*a2[F2 + lane + 32];
#pragma unroll
    for (int o = 16; o; o >>= 1) {
        s  += __shfl_xor_sync(FULL, s, o);
        tn += __shfl_xor_sync(FULL, tn, o);
    }
    if (!lane) { g_as2[w] = s; g_an2[w] = tn; }
}

// ---------------- fused gather1: single-pass softmax, fp16-split store -------
__global__ void gather1() {
    int t = blockIdx.x * blockDim.x + threadIdx.x;
    int w = t >> 5, lane = t & 31;
    if (w >= N_NODES*H1) return;
    int n = w >> 3, h = w & 7;
    int beg = g_rowptr[n], end = g_rowptr[n + 1];
    float as = g_as1[n*H1 + h];

    const int half = lane >> 4;
    const int fl2 = (lane & 15) * 2;
    const __half2* projh = g_P1h + h*(F1/2) + fl2;
    float a0 = 0.f, a1v = 0.f, a2v = 0.f, a3 = 0.f, den = 0.f;
    for (int base = beg; base < end; base += 32) {
        int i = base + lane;
        int s = 0; float wgt = 0.f;
        if (i < end) {
            s = g_nbr[i];
            float v = as + g_an1[s*H1 + h];
            v = (v >= 0.f) ? v : NEG_SLOPE*v;
            wgt = __expf(v);
            den += wgt;
        }
        int cnt = min(32, end - base);
        if (cnt == 32) {
#pragma unroll
            for (int j = 0; j < 16; j++) {
                int sl = 2*j + half;
                float ww = __shfl_sync(FULL, wgt, sl);
                int ss = __shfl_sync(FULL, s, sl);
                uint2 u = *(const uint2*)&projh[(size_t)ss*(C1/2)];
                float2 f0 = __half22float2(*reinterpret_cast<__half2*>(&u.x));
                float2 f1 = __half22float2(*reinterpret_cast<__half2*>(&u.y));
                a0 += ww*f0.x; a1v += ww*f0.y; a2v += ww*f1.x; a3 += ww*f1.y;
            }
        } else {
            int jmax = (cnt + 1) >> 1;
            for (int j = 0; j < jmax; j++) {
                int sl = 2*j + half;
                float ww = __shfl_sync(FULL, wgt, sl);
                int ss = __shfl_sync(FULL, s, sl);
                uint2 u = *(const uint2*)&projh[(size_t)ss*(C1/2)];
                float2 f0 = __half22float2(*reinterpret_cast<__half2*>(&u.x));
                float2 f1 = __half22float2(*reinterpret_cast<__half2*>(&u.y));
                a0 += ww*f0.x; a1v += ww*f0.y; a2v += ww*f1.x; a3 += ww*f1.y;
            }
        }
    }
    a0  += __shfl_xor_sync(FULL, a0, 16);
    a1v += __shfl_xor_sync(FULL, a1v, 16);
    a2v += __shfl_xor_sync(FULL, a2v, 16);
    a3  += __shfl_xor_sync(FULL, a3, 16);
#pragma unroll
    for (int o = 16; o; o >>= 1) den += __shfl_xor_sync(FULL, den, o);
    if (lane < 16) {
        float inv = 1.f / den;
        a0 *= inv; a1v *= inv; a2v *= inv; a3 *= inv;
        a0  = (a0  > 0.f) ? a0  : expm1f(a0);
        a1v = (a1v > 0.f) ? a1v : expm1f(a1v);
        a2v = (a2v > 0.f) ? a2v : expm1f(a2v);
        a3  = (a3  > 0.f) ? a3  : expm1f(a3);
        size_t kp0 = (size_t)n*(C1/2) + ((h*F1 + fl2*2) >> 1);
        uint32_t h0, l0, h1, l1;
        split_pack_f16(a0, a1v, h0, l0);
        split_pack_f16(a2v, a3, h1, l1);
        *(uint2*)&g_HH[kp0] = make_uint2(h0, h1);
        *(uint2*)&g_HL[kp0] = make_uint2(l0, l1);
    }
}

// ---------------- fused gather layer 2 (single-pass, fp32 features) ----------
__global__ void gather2(float* __restrict__ out) {
    int t = blockIdx.x * blockDim.x + threadIdx.x;
    int w = t >> 5, lane = t & 31;
    if (w >= N_NODES) return;
    int n = w;
    int beg = g_rowptr[n], end = g_rowptr[n + 1];
    float as = g_as2[n];

    const int half = lane >> 4;
    const int fl = (lane & 15) * 4;
    const float* projl = g_proj2 + fl;
    float a0 = 0.f, a1v = 0.f, a2v = 0.f, a3 = 0.f, den = 0.f;
    for (int base = beg; base < end; base += 32) {
        int i = base + lane;
        int s = 0; float wgt = 0.f;
        if (i < end) {
            s = g_nbr[i];
            float v = as + g_an2[s];
            v = (v >= 0.f) ? v : NEG_SLOPE*v;
            wgt = __expf(v);
            den += wgt;
        }
        int cnt = min(32, end - base);
        if (cnt == 32) {
#pragma unroll
            for (int j = 0; j < 16; j++) {
                int sl = 2*j + half;
                float ww = __shfl_sync(FULL, wgt, sl);
                int ss = __shfl_sync(FULL, s, sl);
                float4 p = *(const float4*)&projl[(size_t)ss*F2];
                a0 += ww*p.x; a1v += ww*p.y; a2v += ww*p.z; a3 += ww*p.w;
            }
        } else {
            int jmax = (cnt + 1) >> 1;
            for (int j = 0; j < jmax; j++) {
                int sl = 2*j + half;
                float ww = __shfl_sync(FULL, wgt, sl);
                int ss = __shfl_sync(FULL, s, sl);
                float4 p = *(const float4*)&projl[(size_t)ss*F2];
                a0 += ww*p.x; a1v += ww*p.y; a2v += ww*p.z; a3 += ww*p.w;
            }
        }
    }
    a0  += __shfl_xor_sync(FULL, a0, 16);
    a1v += __shfl_xor_sync(FULL, a1v, 16);
    a2v += __shfl_xor_sync(FULL, a2v, 16);
    a3  += __shfl_xor_sync(FULL, a3, 16);
#pragma unroll
    for (int o = 16; o; o >>= 1) den += __shfl_xor_sync(FULL, den, o);
    if (lane < 16) {
        float inv = 1.f / den;
        *(float4*)&out[(size_t)n*F2 + fl] =
            make_float4(a0*inv, a1v*inv, a2v*inv, a3*inv);
    }
}

// ---------------- launch -------------------------------------------------------
extern "C" void kernel_launch(void* const* d_in, const int* in_sizes, int n_in,
                              void* d_out, int out_size) {
    const float* x     = (const float*)d_in[0];
    const int*   edges = (const int*)d_in[1];
    const float* W1    = (const float*)d_in[2];
    const float* a1    = (const float*)d_in[3];
    const float* W2    = (const float*)d_in[4];
    const float* a2    = (const float*)d_in[5];
    float* out = (float*)d_out;

    static cudaStream_t s2 = nullptr;
    static cudaEvent_t evFork = nullptr, evCSR = nullptr;
    if (s2 == nullptr) {
        cudaStreamCreateWithFlags(&s2, cudaStreamNonBlocking);
        cudaEventCreateWithFlags(&evFork, cudaEventDisableTiming);
        cudaEventCreateWithFlags(&evCSR, cudaEventDisableTiming);
    }

    void* cnt_ptr = nullptr;
    cudaGetSymbolAddress(&cnt_ptr, g_cnt);

    // fork: CSR build + W2 convert on s2, concurrent with x-split+gemm1
    cudaEventRecord(evFork, 0);
    cudaStreamWaitEvent(s2, evFork, 0);

    cudaMemsetAsync(cnt_ptr, 0, N_NODES*sizeof(int), s2);
    prep_edges<<<(NE + 255)/256, 256, 0, s2>>>(edges, W2);
    scan_kernel<<<1, 1024, 0, s2>>>();
    fill_csr<<<(NE + 255)/256, 256, 0, s2>>>();
    cudaEventRecord(evCSR, s2);

    // x-split: 80000 lead threads, 4 quads each (MLP=4); W1 needs 32768 threads
    prep_splits<<<(NXP/8 + 255)/256 > ((DIN/2)*C1 + 255)/256 ?
                  (NXP/8 + 255)/256 : ((DIN/2)*C1 + 255)/256, 256>>>(W1, x);
    gemm1_kernel<<<dim3(H1, (N_NODES + 127)/128), 256>>>(a1);

    // join: gather1 needs CSR + gemm1
    cudaStreamWaitEvent(0, evCSR, 0);
    gather1<<<(N_NODES*H1*32 + 255)/256, 256>>>();

    // layer 2
    gemm2_kernel<<<dim3(ZK2, (N_NODES + 127)/128), 256>>>();
    alpha2_combine<<<(N_NODES*32 + 255)/256, 256>>>(a2);
    gather2<<<(N_NODES*32 + 255)/256, 256>>>(out);
}

// round 17
// speedup vs baseline: 1.1078x; 1.0393x over previous
#include <cuda_runtime.h>
#include <cuda_fp16.h>
#include <cstdint>

#define N_NODES 10000
#define DIN 128
#define H1 8
#define F1 64
#define C1 512            // H1*F1
#define E0 80000
#define NE (2*E0 + N_NODES)   // 170000
#define F2 64
#define NEG_SLOPE 0.2f
#define FULL 0xffffffffu
#define ZK2 4                    // gemm2 split-K planes

// ---------------- scratch (static device globals; no allocation) -------------
static __device__ int      g_src[NE];
static __device__ int      g_dst[NE];
static __device__ int      g_cnt[N_NODES];
static __device__ int      g_cursor[N_NODES];
static __device__ int      g_rowptr[N_NODES + 1];
static __device__ int      g_nbr[NE];              // CSR by dst: src indices
static __device__ uint32_t g_B1H[(DIN/2)*C1];      // W1 fp16 plane, kpair-major
static __device__ uint32_t g_B2H[(C1/2)*F2];       // W2 fp16 plane, kpair-major
static __device__ __half2  g_P1h[N_NODES*(C1/2)];  // proj1 as fp16 pairs (gather feed)
static __device__ float    g_as1[N_NODES*H1];
static __device__ float    g_an1[N_NODES*H1];
static __device__ uint32_t g_HH[N_NODES*(C1/2)];   // hbuf fp16-split hi (from gather1)
static __device__ uint32_t g_HL[N_NODES*(C1/2)];   // hbuf fp16-split lo
static __device__ float    g_p2part[ZK2*N_NODES*F2]; // gemm2 split-K partials
static __device__ float    g_proj2[N_NODES*F2];
static __device__ float    g_as2[N_NODES];
static __device__ float    g_an2[N_NODES];

// fp16 split: v = hi + lo
__device__ __forceinline__ void split_pack_f16(float v0, float v1,
                                               uint32_t& hi, uint32_t& lo) {
    __half2 h2 = __floats2half2_rn(v0, v1);
    float r0 = v0 - __half2float(__low2half(h2));
    float r1 = v1 - __half2float(__high2half(h2));
    __half2 l2 = __floats2half2_rn(r0, r1);
    hi = *(const uint32_t*)&h2;
    lo = *(const uint32_t*)&l2;
}

// ---------------- prep A: edges + degree + W2 fp16 (stream 2) ----------------
__global__ void prep_edges(const int* __restrict__ e32,
                           const float* __restrict__ W2) {
    int i = blockIdx.x * blockDim.x + threadIdx.x;
    if (i < NE) {
        bool is64 = (e32[1] == 0) && (e32[3] == 0) && (e32[5] == 0) && (e32[7] == 0);
        int s, d;
        if (i < NE - N_NODES) {
            int j  = (i < E0) ? i : (i - E0);
            int si = (i < E0) ? j : (E0 + j);
            int di = (i < E0) ? (E0 + j) : j;
            s = is64 ? e32[2*si] : e32[si];
            d = is64 ? e32[2*di] : e32[di];
        } else {
            s = i - (NE - N_NODES); d = s;
        }
        s = min(max(s, 0), N_NODES - 1);
        d = min(max(d, 0), N_NODES - 1);
        g_src[i] = s; g_dst[i] = d;
        atomicAdd(&g_cnt[d], 1);
    }
    // W2 (C1,F2) -> fp16 plane, kpair-major
    if (i < (C1/2)*F2) {
        int kp = i / F2, c = i % F2;
        __half2 h2 = __floats2half2_rn(W2[(2*kp)*F2 + c],
                                       W2[(2*kp + 1)*F2 + c]);
        g_B2H[i] = *(const uint32_t*)&h2;
    }
}

// ---------------- prep B: W1 fp16 only (tiny, main stream) -------------------
__global__ void w1_prep(const float* __restrict__ W1) {
    int i = blockIdx.x * blockDim.x + threadIdx.x;
    if (i >= (DIN/2)*C1) return;
    int kp = i / C1, c = i % C1;
    int h = c >> 6, f = c & 63;
    __half2 h2 = __floats2half2_rn(W1[(h*DIN + 2*kp)*F1 + f],
                                   W1[(h*DIN + 2*kp + 1)*F1 + f]);
    g_B1H[i] = *(const uint32_t*)&h2;
}

// ---------------- exclusive scan of in-degrees (single block) ----------------
__global__ void scan_kernel() {
    __shared__ int ssum[1024];
    const int t = threadIdx.x;
    const int per = (N_NODES + 1023) / 1024;   // 10
    int base = t * per;
    int loc[16];
    int s = 0;
#pragma unroll
    for (int i = 0; i < per; i++) {
        int idx = base + i;
        int v = (idx < N_NODES) ? g_cnt[idx] : 0;
        loc[i] = v; s += v;
    }
    ssum[t] = s;
    __syncthreads();
    for (int off = 1; off < 1024; off <<= 1) {
        int v = (t >= off) ? ssum[t - off] : 0;
        __syncthreads();
        ssum[t] += v;
        __syncthreads();
    }
    int run = (t > 0) ? ssum[t - 1] : 0;
#pragma unroll
    for (int i = 0; i < per; i++) {
        int idx = base + i;
        if (idx < N_NODES) { g_rowptr[idx] = run; g_cursor[idx] = run; run += loc[i]; }
    }
    if (t == 1023) g_rowptr[N_NODES] = NE;
}

__global__ void fill_csr() {
    int e = blockIdx.x * blockDim.x + threadIdx.x;
    if (e >= NE) return;
    int d = g_dst[e];
    int slot = atomicAdd(&g_cursor[d], 1);
    g_nbr[slot] = g_src[e];
}

// ---------------- fp16 tensor-core MMA (m16n8k16) -----------------------------
#define MMA_F16(D, A0, A1, A2, A3, B0, B1) \
    asm("mma.sync.aligned.m16n8k16.row.col.f32.f16.f16.f32 " \
        "{%0,%1,%2,%3}, {%4,%5,%6,%7}, {%8,%9}, {%0,%1,%2,%3};" \
        : "+f"(D[0]), "+f"(D[1]), "+f"(D[2]), "+f"(D[3]) \
        : "r"(A0), "r"(A1), "r"(A2), "r"(A3), "r"(B0), "r"(B1))

// ---------------- GEMM1: 128x64 tile, in-kernel fp16-x2 A split, fused alpha1
__global__ __launch_bounds__(256) void gemm1_kernel(const float* __restrict__ A,
                                                    const float* __restrict__ a1) {
    __shared__ uint32_t AsH[128][12], AsL[128][12];
    __shared__ uint32_t BsH[64][12];
    __shared__ float sAs[64], sAn[64];
    __shared__ float salS[128][2], salN[128][2];

    const int tid = threadIdx.x;
    const int lane = tid & 31, wid = tid >> 5;
    const int wm = wid >> 1, wn = wid & 1;
    const int g = lane >> 2, tig = lane & 3;
    const int row0 = blockIdx.y * 128;
    const int h = blockIdx.x;
    const int col0 = h * 64;
    const int M = N_NODES;

    if (tid < 64) {
        sAs[tid] = __ldg(&a1[h*2*F1 + tid]);
        sAn[tid] = __ldg(&a1[h*2*F1 + F1 + tid]);
    }

    float acc[2][4][4];
#pragma unroll
    for (int mi = 0; mi < 2; mi++)
#pragma unroll
        for (int ni = 0; ni < 4; ni++)
#pragma unroll
            for (int q = 0; q < 4; q++) acc[mi][ni][q] = 0.f;

    for (int k0 = 0; k0 < DIN; k0 += 16) {
        const int kpb = k0 >> 1;
        // A tile: load fp32 x, split to fp16 hi/lo in-kernel
#pragma unroll
        for (int t = 0; t < 4; t++) {
            int idx = tid + t*256;
            int r = idx >> 3, kk = idx & 7;
            int grow = row0 + r;
            float2 v = (grow < M) ? *(const float2*)&A[(size_t)grow*DIN + k0 + 2*kk]
                                  : make_float2(0.f, 0.f);
            split_pack_f16(v.x, v.y, AsH[r][kk], AsL[r][kk]);
        }
#pragma unroll
        for (int t = 0; t < 2; t++) {
            int idx = tid + t*256;
            int kk = idx >> 6, c = idx & 63;
            BsH[c][kk] = g_B1H[(size_t)(kpb + kk)*C1 + col0 + c];
        }
        __syncthreads();

        uint32_t bh[4][2];
#pragma unroll
        for (int ni = 0; ni < 4; ni++) {
            int c = wn*32 + ni*8 + g;
            bh[ni][0] = BsH[c][tig];     bh[ni][1] = BsH[c][tig + 4];
        }
#pragma unroll
        for (int mi = 0; mi < 2; mi++) {
            int r = wm*32 + mi*16 + g;
            uint32_t ah0 = AsH[r][tig],     ah1 = AsH[r + 8][tig];
            uint32_t ah2 = AsH[r][tig + 4], ah3 = AsH[r + 8][tig + 4];
            uint32_t al0 = AsL[r][tig],     al1 = AsL[r + 8][tig];
            uint32_t al2 = AsL[r][tig + 4], al3 = AsL[r + 8][tig + 4];
#pragma unroll
            for (int ni = 0; ni < 4; ni++) {
                MMA_F16(acc[mi][ni], ah0, ah1, ah2, ah3, bh[ni][0], bh[ni][1]);
                MMA_F16(acc[mi][ni], al0, al1, al2, al3, bh[ni][0], bh[ni][1]);
            }
        }
        __syncthreads();
    }

    // epilogue: fp16 proj1 store + fused alpha1 (fp32)
#pragma unroll
    for (int mi = 0; mi < 2; mi++) {
        float s0 = 0.f, s8 = 0.f, n0 = 0.f, n8 = 0.f;
        int growA = row0 + wm*32 + mi*16 + g;
        int growB = growA + 8;
#pragma unroll
        for (int ni = 0; ni < 4; ni++) {
            float c0 = acc[mi][ni][0], c1 = acc[mi][ni][1];
            float c2 = acc[mi][ni][2], c3 = acc[mi][ni][3];
            int cl = wn*32 + ni*8 + 2*tig;
            size_t cp = (size_t)(col0 + cl) >> 1;
            if (growA < M)
                g_P1h[(size_t)growA*(C1/2) + cp] = __floats2half2_rn(c0, c1);
            if (growB < M)
                g_P1h[(size_t)growB*(C1/2) + cp] = __floats2half2_rn(c2, c3);
            float as0 = sAs[cl], as1 = sAs[cl + 1];
            float an0 = sAn[cl], an1 = sAn[cl + 1];
            s0 += c0*as0 + c1*as1;  n0 += c0*an0 + c1*an1;
            s8 += c2*as0 + c3*as1;  n8 += c2*an0 + c3*an1;
        }
#pragma unroll
        for (int o = 1; o <= 2; o <<= 1) {
            s0 += __shfl_xor_sync(FULL, s0, o);
            s8 += __shfl_xor_sync(FULL, s8, o);
            n0 += __shfl_xor_sync(FULL, n0, o);
            n8 += __shfl_xor_sync(FULL, n8, o);
        }
        if (tig == 0) {
            int rl = wm*32 + mi*16 + g;
            salS[rl][wn] = s0;  salN[rl][wn] = n0;
            salS[rl + 8][wn] = s8;  salN[rl + 8][wn] = n8;
        }
    }
    __syncthreads();
    if (tid < 128) {
        int grow = row0 + tid;
        if (grow < M) {
            g_as1[grow*H1 + h] = salS[tid][0] + salS[tid][1];
            g_an1[grow*H1 + h] = salN[tid][0] + salN[tid][1];
        }
    }
}

// ---------------- GEMM2: fp16-x2 MMA, split-K z=4, pre-split A ---------------
__global__ __launch_bounds__(256) void gemm2_kernel() {
    __shared__ uint32_t AsH[128][12], AsL[128][12];
    __shared__ uint32_t BsH[64][12];

    const int tid = threadIdx.x;
    const int lane = tid & 31, wid = tid >> 5;
    const int wm = wid >> 1, wn = wid & 1;
    const int g = lane >> 2, tig = lane & 3;
    const int row0 = blockIdx.y * 128;
    const int z = blockIdx.x;
    const int M = N_NODES;
    float* C = g_p2part + (size_t)z * N_NODES * F2;

    float acc[2][4][4];
#pragma unroll
    for (int mi = 0; mi < 2; mi++)
#pragma unroll
        for (int ni = 0; ni < 4; ni++)
#pragma unroll
            for (int q = 0; q < 4; q++) acc[mi][ni][q] = 0.f;

    const int kbeg = z * (C1/ZK2);
    for (int k0 = kbeg; k0 < kbeg + C1/ZK2; k0 += 16) {
        const int kpb = k0 >> 1;
#pragma unroll
        for (int t = 0; t < 4; t++) {
            int idx = tid + t*256;
            int r = idx >> 3, kk = idx & 7;
            int grow = row0 + r;
            if (grow < M) {
                size_t gi = (size_t)grow*(C1/2) + kpb + kk;
                AsH[r][kk] = g_HH[gi];
                AsL[r][kk] = g_HL[gi];
            } else {
                AsH[r][kk] = 0u; AsL[r][kk] = 0u;
            }
        }
#pragma unroll
        for (int t = 0; t < 2; t++) {
            int idx = tid + t*256;
            int kk = idx >> 6, c = idx & 63;
            BsH[c][kk] = g_B2H[(size_t)(kpb + kk)*F2 + c];
        }
        __syncthreads();

        uint32_t bh[4][2];
#pragma unroll
        for (int ni = 0; ni < 4; ni++) {
            int c = wn*32 + ni*8 + g;
            bh[ni][0] = BsH[c][tig];     bh[ni][1] = BsH[c][tig + 4];
        }
#pragma unroll
        for (int mi = 0; mi < 2; mi++) {
            int r = wm*32 + mi*16 + g;
            uint32_t ah0 = AsH[r][tig],     ah1 = AsH[r + 8][tig];
            uint32_t ah2 = AsH[r][tig + 4], ah3 = AsH[r + 8][tig + 4];
            uint32_t al0 = AsL[r][tig],     al1 = AsL[r + 8][tig];
            uint32_t al2 = AsL[r][tig + 4], al3 = AsL[r + 8][tig + 4];
#pragma unroll
            for (int ni = 0; ni < 4; ni++) {
                MMA_F16(acc[mi][ni], ah0, ah1, ah2, ah3, bh[ni][0], bh[ni][1]);
                MMA_F16(acc[mi][ni], al0, al1, al2, al3, bh[ni][0], bh[ni][1]);
            }
        }
        __syncthreads();
    }

#pragma unroll
    for (int mi = 0; mi < 2; mi++) {
        int growA = row0 + wm*32 + mi*16 + g;
        int growB = growA + 8;
#pragma unroll
        for (int ni = 0; ni < 4; ni++) {
            int cl = wn*32 + ni*8 + 2*tig;
            if (growA < M)
                *(float2*)&C[(size_t)growA*F2 + cl] =
                    make_float2(acc[mi][ni][0], acc[mi][ni][1]);
            if (growB < M)
                *(float2*)&C[(size_t)growB*F2 + cl] =
                    make_float2(acc[mi][ni][2], acc[mi][ni][3]);
        }
    }
}

// ---------------- combine split-K partials + attention (layer 2) -------------
__global__ void alpha2_combine(const float* __restrict__ a2) {
    int t = blockIdx.x * blockDim.x + threadIdx.x;
    int w = t >> 5, lane = t & 31;
    if (w >= N_NODES) return;
    const size_t NF = (size_t)N_NODES * F2;
    size_t base = (size_t)w*F2;
    float v0 = 0.f, v1 = 0.f;
#pragma unroll
    for (int z = 0; z < ZK2; z++) {
        v0 += g_p2part[z*NF + base + lane];
        v1 += g_p2part[z*NF + base + lane + 32];
    }
    g_proj2[base + lane] = v0;
    g_proj2[base + lane + 32] = v1;
    float s  = v0*a2[lane]      + v1*a2[lane + 32];
    float tn = v0*a2[F2 + lane] + v1*a2[F2 + lane + 32];
#pragma unroll
    for (int o = 16; o; o >>= 1) {
        s  += __shfl_xor_sync(FULL, s, o);
        tn += __shfl_xor_sync(FULL, tn, o);
    }
    if (!lane) { g_as2[w] = s; g_an2[w] = tn; }
}

// ---------------- fused gather1: single-pass softmax, fp16-split store -------
__global__ void gather1() {
    int t = blockIdx.x * blockDim.x + threadIdx.x;
    int w = t >> 5, lane = t & 31;
    if (w >= N_NODES*H1) return;
    int n = w >> 3, h = w & 7;
    int beg = g_rowptr[n], end = g_rowptr[n + 1];
    float as = g_as1[n*H1 + h];

    const int half = lane >> 4;
    const int fl2 = (lane & 15) * 2;
    const __half2* projh = g_P1h + h*(F1/2) + fl2;
    float a0 = 0.f, a1v = 0.f, a2v = 0.f, a3 = 0.f, den = 0.f;
    for (int base = beg; base < end; base += 32) {
        int i = base + lane;
        int s = 0; float wgt = 0.f;
        if (i < end) {
            s = g_nbr[i];
            float v = as + g_an1[s*H1 + h];
            v = (v >= 0.f) ? v : NEG_SLOPE*v;
            wgt = __expf(v);
            den += wgt;
        }
        int cnt = min(32, end - base);
        if (cnt == 32) {
#pragma unroll
            for (int j = 0; j < 16; j++) {
                int sl = 2*j + half;
                float ww = __shfl_sync(FULL, wgt, sl);
                int ss = __shfl_sync(FULL, s, sl);
                uint2 u = *(const uint2*)&projh[(size_t)ss*(C1/2)];
                float2 f0 = __half22float2(*reinterpret_cast<__half2*>(&u.x));
                float2 f1 = __half22float2(*reinterpret_cast<__half2*>(&u.y));
                a0 += ww*f0.x; a1v += ww*f0.y; a2v += ww*f1.x; a3 += ww*f1.y;
            }
        } else {
            int jmax = (cnt + 1) >> 1;
            for (int j = 0; j < jmax; j++) {
                int sl = 2*j + half;
                float ww = __shfl_sync(FULL, wgt, sl);
                int ss = __shfl_sync(FULL, s, sl);
                uint2 u = *(const uint2*)&projh[(size_t)ss*(C1/2)];
                float2 f0 = __half22float2(*reinterpret_cast<__half2*>(&u.x));
                float2 f1 = __half22float2(*reinterpret_cast<__half2*>(&u.y));
                a0 += ww*f0.x; a1v += ww*f0.y; a2v += ww*f1.x; a3 += ww*f1.y;
            }
        }
    }
    a0  += __shfl_xor_sync(FULL, a0, 16);
    a1v += __shfl_xor_sync(FULL, a1v, 16);
    a2v += __shfl_xor_sync(FULL, a2v, 16);
    a3  += __shfl_xor_sync(FULL, a3, 16);
#pragma unroll
    for (int o = 16; o; o >>= 1) den += __shfl_xor_sync(FULL, den, o);
    if (lane < 16) {
        float inv = 1.f / den;
        a0 *= inv; a1v *= inv; a2v *= inv; a3 *= inv;
        a0  = (a0  > 0.f) ? a0  : expm1f(a0);
        a1v = (a1v > 0.f) ? a1v : expm1f(a1v);
        a2v = (a2v > 0.f) ? a2v : expm1f(a2v);
        a3  = (a3  > 0.f) ? a3  : expm1f(a3);
        size_t kp0 = (size_t)n*(C1/2) + ((h*F1 + fl2*2) >> 1);
        uint32_t h0, l0, h1, l1;
        split_pack_f16(a0, a1v, h0, l0);
        split_pack_f16(a2v, a3, h1, l1);
        *(uint2*)&g_HH[kp0] = make_uint2(h0, h1);
        *(uint2*)&g_HL[kp0] = make_uint2(l0, l1);
    }
}

// ---------------- fused gather layer 2 (single-pass, fp32 features) ----------
__global__ void gather2(float* __restrict__ out) {
    int t = blockIdx.x * blockDim.x + threadIdx.x;
    int w = t >> 5, lane = t & 31;
    if (w >= N_NODES) return;
    int n = w;
    int beg = g_rowptr[n], end = g_rowptr[n + 1];
    float as = g_as2[n];

    const int half = lane >> 4;
    const int fl = (lane & 15) * 4;
    const float* projl = g_proj2 + fl;
    float a0 = 0.f, a1v = 0.f, a2v = 0.f, a3 = 0.f, den = 0.f;
    for (int base = beg; base < end; base += 32) {
        int i = base + lane;
        int s = 0; float wgt = 0.f;
        if (i < end) {
            s = g_nbr[i];
            float v = as + g_an2[s];
            v = (v >= 0.f) ? v : NEG_SLOPE*v;
            wgt = __expf(v);
            den += wgt;
        }
        int cnt = min(32, end - base);
        if (cnt == 32) {
#pragma unroll
            for (int j = 0; j < 16; j++) {
                int sl = 2*j + half;
                float ww = __shfl_sync(FULL, wgt, sl);
                int ss = __shfl_sync(FULL, s, sl);
                float4 p = *(const float4*)&projl[(size_t)ss*F2];
                a0 += ww*p.x; a1v += ww*p.y; a2v += ww*p.z; a3 += ww*p.w;
            }
        } else {
            int jmax = (cnt + 1) >> 1;
            for (int j = 0; j < jmax; j++) {
                int sl = 2*j + half;
                float ww = __shfl_sync(FULL, wgt, sl);
                int ss = __shfl_sync(FULL, s, sl);
                float4 p = *(const float4*)&projl[(size_t)ss*F2];
                a0 += ww*p.x; a1v += ww*p.y; a2v += ww*p.z; a3 += ww*p.w;
            }
        }
    }
    a0  += __shfl_xor_sync(FULL, a0, 16);
    a1v += __shfl_xor_sync(FULL, a1v, 16);
    a2v += __shfl_xor_sync(FULL, a2v, 16);
    a3  += __shfl_xor_sync(FULL, a3, 16);
#pragma unroll
    for (int o = 16; o; o >>= 1) den += __shfl_xor_sync(FULL, den, o);
    if (lane < 16) {
        float inv = 1.f / den;
        *(float4*)&out[(size_t)n*F2 + fl] =
            make_float4(a0*inv, a1v*inv, a2v*inv, a3*inv);
    }
}

// ---------------- launch -------------------------------------------------------
extern "C" void kernel_launch(void* const* d_in, const int* in_sizes, int n_in,
                              void* d_out, int out_size) {
    const float* x     = (const float*)d_in[0];
    const int*   edges = (const int*)d_in[1];
    const float* W1    = (const float*)d_in[2];
    const float* a1    = (const float*)d_in[3];
    const float* W2    = (const float*)d_in[4];
    const float* a2    = (const float*)d_in[5];
    float* out = (float*)d_out;

    static cudaStream_t s2 = nullptr;
    static cudaEvent_t evFork = nullptr, evCSR = nullptr;
    if (s2 == nullptr) {
        cudaStreamCreateWithFlags(&s2, cudaStreamNonBlocking);
        cudaEventCreateWithFlags(&evFork, cudaEventDisableTiming);
        cudaEventCreateWithFlags(&evCSR, cudaEventDisableTiming);
    }

    void* cnt_ptr = nullptr;
    cudaGetSymbolAddress(&cnt_ptr, g_cnt);

    // fork: CSR build + W2 convert on s2, concurrent with W1-convert+gemm1
    cudaEventRecord(evFork, 0);
    cudaStreamWaitEvent(s2, evFork, 0);

    cudaMemsetAsync(cnt_ptr, 0, N_NODES*sizeof(int), s2);
    prep_edges<<<(NE + 255)/256, 256, 0, s2>>>(edges, W2);
    scan_kernel<<<1, 1024, 0, s2>>>();
    fill_csr<<<(NE + 255)/256, 256, 0, s2>>>();
    cudaEventRecord(evCSR, s2);

    // main: tiny W1 convert, then gemm1 (x split in-kernel)
    w1_prep<<<((DIN/2)*C1 + 255)/256, 256>>>(W1);
    gemm1_kernel<<<dim3(H1, (N_NODES + 127)/128), 256>>>(x, a1);

    // join: gather1 needs CSR + gemm1
    cudaStreamWaitEvent(0, evCSR, 0);
    gather1<<<(N_NODES*H1*32 + 255)/256, 256>>>();

    // layer 2
    gemm2_kernel<<<dim3(ZK2, (N_NODES + 127)/128), 256>>>();
    alpha2_combine<<<(N_NODES*32 + 255)/256, 256>>>(a2);
    gather2<<<(N_NODES*32 + 255)/256, 256>>>(out);
}